// round 10
// baseline (speedup 1.0000x reference)
#include <cuda_runtime.h>
#include <cuda_fp16.h>
#include <cstdint>

#define B_    4
#define C_    64
#define H_    128
#define W_    128
#define HW_   16384
#define COUT_ 64
#define KK_   9

// ---- smem byte layout (main kernel) ----
#define S_OFF      0          // S fp16, 2 stages x (256 rows x 128B) = 64KB, XOR-swizzled
#define W_BASE     65536      // W fp16, 3 stages x 8KB
#define CD_BASE    90112      // coords, 2 stages x 8KB (sw 4KB + sidx 4KB)
#define SMEM_BYTES 106496

// ---- scratch (__device__ globals: allocation-free rule) ----
__device__ __half g_xh[(size_t)B_ * HW_ * C_];                   // NHWC fp16
__device__ __align__(16) unsigned char g_w[KK_ * 8192];          // per tap: fp16 [co][c], pre-swizzled

// ---------------- helpers ----------------
__device__ __forceinline__ uint32_t smem_u32(const void* p) {
    uint32_t a;
    asm("{ .reg .u64 t; cvta.to.shared.u64 t, %1; cvt.u32.u64 %0, t; }" : "=r"(a) : "l"(p));
    return a;
}
__device__ __forceinline__ uint32_t pack_f16(float lo, float hi) {
    uint32_t r;
    asm("cvt.rn.f16x2.f32 %0, %1, %2;" : "=r"(r) : "f"(hi), "f"(lo));
    return r;
}
__device__ __forceinline__ float2 h2f2(uint32_t h2) {
    float lo, hi;
    asm("{ .reg .f16 a, b; mov.b32 {a, b}, %2; cvt.f32.f16 %0, a; cvt.f32.f16 %1, b; }"
        : "=f"(lo), "=f"(hi) : "r"(h2));
    return make_float2(lo, hi);
}
__device__ __forceinline__ void ldsm_x4(uint32_t* r, uint32_t addr) {
    asm volatile("ldmatrix.sync.aligned.m8n8.x4.shared.b16 {%0,%1,%2,%3}, [%4];"
                 : "=r"(r[0]), "=r"(r[1]), "=r"(r[2]), "=r"(r[3]) : "r"(addr));
}
__device__ __forceinline__ void mma_f16(float* d, const uint32_t* a, uint32_t b0, uint32_t b1) {
    asm volatile(
        "mma.sync.aligned.m16n8k16.row.col.f32.f16.f16.f32 "
        "{%0,%1,%2,%3}, {%4,%5,%6,%7}, {%8,%9}, {%0,%1,%2,%3};"
        : "+f"(d[0]), "+f"(d[1]), "+f"(d[2]), "+f"(d[3])
        : "r"(a[0]), "r"(a[1]), "r"(a[2]), "r"(a[3]), "r"(b0), "r"(b1));
}
__device__ __forceinline__ void cp_async16(uint32_t dst, const void* src) {
    asm volatile("cp.async.ca.shared.global [%0], [%1], 16;" :: "r"(dst), "l"(src) : "memory");
}

// ---------------- prepass: NCHW f32 -> NHWC fp16 (vectorized stores) ----------------
// Tile: 32 channels x 128 pixels per block. Row = 136 floats (544B, 16B-aligned bases).
__global__ void transpose_x_kernel(const float* __restrict__ x) {
    __shared__ float tile[32][136];
    const int b    = blockIdx.z;
    const int pix0 = blockIdx.x * 128;
    const int c0   = blockIdx.y * 32;
    const int tid  = threadIdx.x;
    const int rr   = tid >> 5;           // 0..7
    const int f4   = tid & 31;           // float4 column 0..31
#pragma unroll
    for (int i = 0; i < 4; ++i) {
        int r = rr + 8 * i;
        float4 v = *(const float4*)&x[(size_t)(b * C_ + c0 + r) * HW_ + pix0 + f4 * 4];
        *(float4*)&tile[r][f4 * 4] = v;
    }
    __syncthreads();
    // store: 128 px x 8 quad-groups (4 ch) as uint2; lanes qg-major -> 64B-contiguous
#pragma unroll
    for (int i = 0; i < 4; ++i) {
        int idx = tid + 256 * i;         // 0..1023
        int qg  = idx & 7;
        int px  = idx >> 3;
        int c   = qg * 4;
        uint32_t h0 = pack_f16(tile[c + 0][px], tile[c + 1][px]);
        uint32_t h1 = pack_f16(tile[c + 2][px], tile[c + 3][px]);
        *(uint2*)&g_xh[(size_t)(b * HW_ + pix0 + px) * C_ + c0 + c] = make_uint2(h0, h1);
    }
}

// ---------------- prepass: weight -> fp16, swizzled [k][co][c] ----------------
__global__ void prep_w_kernel(const float* __restrict__ w) {
    int t = blockIdx.x * blockDim.x + threadIdx.x;
    if (t >= KK_ * COUT_ * C_) return;
    int k  = t >> 12;
    int r  = t & 4095;
    int co = r >> 6;
    int c  = r & 63;
    float v = w[co * (C_ * KK_) + c * KK_ + k];
    int jsw  = (c >> 3) ^ (co & 7);
    int off  = co * 128 + jsw * 16 + (c & 7) * 2;
    *(__half*)(g_w + k * 8192 + off) = __float2half_rn(v);
}

// ---------------- fused deformable conv: single-sync-per-tap pipeline ----------------
// One CTA per (b, ho-pair): M = 256 pixels x 64 cout. 256 threads = 8 warps.
// Iter k: sample(k+1)->S[(k+1)&1] ; GEMM(k)<-S[k&1],W[k%3] ; coords(k+2) ; load_w(k+2) ; sync.
__global__ __launch_bounds__(256, 2) void deform_main_kernel(
    const float* __restrict__ offset,
    const float* __restrict__ mask,
    const float* __restrict__ bias,
    float* __restrict__ out) {
    extern __shared__ char sm[];
    const uint32_t smb = smem_u32(sm);

    const int tid = threadIdx.x;
    const int wid = tid >> 5;
    const int l   = tid & 31;
    const int blk = blockIdx.x;          // 0..255
    const int b   = blk >> 6;
    const int ho0 = (blk & 63) * 2;

    const __half* __restrict__ xb = g_xh + (size_t)b * (HW_ * C_);

    const int pm0 = (wid & 3) * 64;      // 4 M-warps x 2 N-warps; tile 64px x 32co
    const int co0 = (wid >> 2) * 32;
    const int lrow = l & 15, lhi = l >> 4, lm = lrow & 7;

    float acc[4][4][4];
#pragma unroll
    for (int i = 0; i < 4; ++i)
#pragma unroll
        for (int j = 0; j < 4; ++j)
#pragma unroll
            for (int q = 0; q < 4; ++q) acc[i][j][q] = 0.f;

    auto coords = [&](int k) {
        float* sw  = (float*)(sm + CD_BASE + (k & 1) * 8192);
        int* sidx  = (int*)(sm + CD_BASE + (k & 1) * 8192 + 4096);
        const int p   = tid;
        const int row = p >> 7;
        const int ho  = ho0 + row;
        const int wo  = p & 127;
        int obase = ((b * 18 + 2 * k) * 128 + ho) * 128 + wo;
        float dy = offset[obase];
        float dx = offset[obase + HW_];
        float m  = mask[((b * 9 + k) * 128 + ho) * 128 + wo];
        float yy = (float)(ho - 1 + (k / 3)) + dy;
        float xx = (float)(wo - 1 + (k % 3)) + dx;
        float y0f = floorf(yy), x0f = floorf(xx);
        float ly = yy - y0f, lx = xx - x0f;
        int y0 = (int)y0f, x0 = (int)x0f;
        int y1 = y0 + 1,   x1 = x0 + 1;
        bool vy0 = (y0 >= 0) & (y0 < H_), vy1 = (y1 >= 0) & (y1 < H_);
        bool vx0 = (x0 >= 0) & (x0 < W_), vx1 = (x1 >= 0) & (x1 < W_);
        int cy0 = min(max(y0, 0), H_ - 1), cy1 = min(max(y1, 0), H_ - 1);
        int cx0 = min(max(x0, 0), W_ - 1), cx1 = min(max(x1, 0), W_ - 1);
        float w00 = (1.f - ly) * (1.f - lx) * m;
        float w01 = (1.f - ly) * lx * m;
        float w10 = ly * (1.f - lx) * m;
        float w11 = ly * lx * m;
        sw[0 * 256 + p] = (vy0 & vx0) ? w00 : 0.f;
        sw[1 * 256 + p] = (vy0 & vx1) ? w01 : 0.f;
        sw[2 * 256 + p] = (vy1 & vx0) ? w10 : 0.f;
        sw[3 * 256 + p] = (vy1 & vx1) ? w11 : 0.f;
        sidx[0 * 256 + p] = (cy0 * W_ + cx0) * C_;
        sidx[1 * 256 + p] = (cy0 * W_ + cx1) * C_;
        sidx[2 * 256 + p] = (cy1 * W_ + cx0) * C_;
        sidx[3 * 256 + p] = (cy1 * W_ + cx1) * C_;
    };
    auto load_w = [&](int k) {
        uint32_t woff = (uint32_t)(W_BASE + (k % 3) * 8192);
        const unsigned char* src = g_w + k * 8192 + tid * 16;
        cp_async16(smb + woff + tid * 16, src);
        cp_async16(smb + woff + tid * 16 + 4096, src + 4096);
        asm volatile("cp.async.commit_group;" ::: "memory");
    };
    auto sample = [&](int k) {
        const float* sw  = (const float*)(sm + CD_BASE + (k & 1) * 8192);
        const int* sidx  = (const int*)(sm + CD_BASE + (k & 1) * 8192 + 4096);
        char* sdst = sm + S_OFF + (k & 1) * 32768;
#pragma unroll
        for (int it = 0; it < 8; ++it) {
            int u  = tid + 256 * it;   // 8 c8-groups x 256 pixels
            int c8 = u & 7;
            int p  = u >> 3;
            float w0 = sw[p], w1 = sw[256 + p], w2 = sw[512 + p], w3 = sw[768 + p];
            int  i0 = sidx[p], i1 = sidx[256 + p], i2 = sidx[512 + p], i3 = sidx[768 + p];
            const __half* xc = xb + c8 * 8;
            uint4 a0 = *(const uint4*)(xc + i0);
            uint4 a1 = *(const uint4*)(xc + i1);
            uint4 a2 = *(const uint4*)(xc + i2);
            uint4 a3 = *(const uint4*)(xc + i3);
            uint32_t res[4];
#pragma unroll
            for (int q = 0; q < 4; ++q) {
                float2 f0 = h2f2((&a0.x)[q]), f1 = h2f2((&a1.x)[q]);
                float2 f2 = h2f2((&a2.x)[q]), f3 = h2f2((&a3.x)[q]);
                float vlo = w0 * f0.x + w1 * f1.x + w2 * f2.x + w3 * f3.x;
                float vhi = w0 * f0.y + w1 * f1.y + w2 * f2.y + w3 * f3.y;
                res[q] = pack_f16(vlo, vhi);
            }
            int jsw = c8 ^ (p & 7);
            *(uint4*)(sdst + p * 128 + jsw * 16) = make_uint4(res[0], res[1], res[2], res[3]);
        }
    };

    // ---- prologue ----
    coords(0);
    coords(1);
    load_w(0);
    load_w(1);
    asm volatile("cp.async.wait_group 0;" ::: "memory");
    __syncthreads();
    sample(0);
    __syncthreads();

    for (int k = 0; k < KK_; ++k) {
        if (k + 1 < KK_) sample(k + 1);        // gathers issue early; latency hides under GEMM
        if (k + 2 < KK_) { coords(k + 2); load_w(k + 2); }

        // ---- fp16 GEMM(k) via mma.sync ----
        const uint32_t aBase = smb + S_OFF + (uint32_t)(k & 1) * 32768u + (uint32_t)(pm0 + lrow) * 128;
        const uint32_t bBase = smb + (uint32_t)(W_BASE + (k % 3) * 8192) + (uint32_t)(co0 + lrow) * 128;
#pragma unroll
        for (int ks = 0; ks < 4; ++ks) {
            const uint32_t soff = (uint32_t)((((ks << 1) | lhi) ^ lm) << 4);
            uint32_t bh0[4], bh1[4];
            ldsm_x4(bh0, bBase + soff);
            ldsm_x4(bh1, bBase + 2048 + soff);
#pragma unroll
            for (int mf = 0; mf < 4; ++mf) {
                uint32_t ah[4];
                ldsm_x4(ah, aBase + (uint32_t)(mf * 2048) + soff);
                mma_f16(acc[mf][0], ah, bh0[0], bh0[2]);
                mma_f16(acc[mf][1], ah, bh0[1], bh0[3]);
                mma_f16(acc[mf][2], ah, bh1[0], bh1[2]);
                mma_f16(acc[mf][3], ah, bh1[1], bh1[3]);
            }
        }
        asm volatile("cp.async.wait_group 1;" ::: "memory");   // W(k+2) landed by next iter's GEMM
        __syncthreads();
    }

    // ---- epilogue: fragments -> gmem, add bias ----
    const int rr = (l >> 2);
    const int cbase = (l & 3) * 2;
#pragma unroll
    for (int j = 0; j < 4; ++j) {
        int cc = co0 + j * 8 + cbase;
        float b0v = bias[cc], b1v = bias[cc + 1];
        size_t plane0 = (size_t)(b * COUT_ + cc) * HW_;
        size_t plane1 = plane0 + HW_;
#pragma unroll
        for (int mf = 0; mf < 4; ++mf) {
            int px0 = pm0 + mf * 16 + rr;
            int px1 = px0 + 8;
            size_t o00 = plane0 + (size_t)(ho0 + (px0 >> 7)) * W_ + (px0 & 127);
            size_t o01 = plane1 + (size_t)(ho0 + (px0 >> 7)) * W_ + (px0 & 127);
            size_t o10 = plane0 + (size_t)(ho0 + (px1 >> 7)) * W_ + (px1 & 127);
            size_t o11 = plane1 + (size_t)(ho0 + (px1 >> 7)) * W_ + (px1 & 127);
            out[o00] = acc[mf][j][0] + b0v;
            out[o01] = acc[mf][j][1] + b1v;
            out[o10] = acc[mf][j][2] + b0v;
            out[o11] = acc[mf][j][3] + b1v;
        }
    }
}

extern "C" void kernel_launch(void* const* d_in, const int* in_sizes, int n_in,
                              void* d_out, int out_size) {
    const float* x      = (const float*)d_in[0];
    const float* offset = (const float*)d_in[1];
    const float* mask   = (const float*)d_in[2];
    const float* weight = (const float*)d_in[3];
    const float* bias   = (const float*)d_in[4];
    float* out = (float*)d_out;

    transpose_x_kernel<<<dim3(HW_ / 128, C_ / 32, B_), 256>>>(x);
    prep_w_kernel<<<(KK_ * C_ * COUT_ + 255) / 256, 256>>>(weight);

    cudaFuncSetAttribute(deform_main_kernel,
                         cudaFuncAttributeMaxDynamicSharedMemorySize, SMEM_BYTES);
    deform_main_kernel<<<B_ * (H_ / 2), 256, SMEM_BYTES>>>(offset, mask, bias, out);
}

// round 11
// speedup vs baseline: 1.0979x; 1.0979x over previous
#include <cuda_runtime.h>
#include <cuda_fp16.h>
#include <cstdint>

#define B_    4
#define C_    64
#define H_    128
#define W_    128
#define HW_   16384
#define COUT_ 64
#define KK_   9

// ---- smem byte layout ----
#define S_OFF      0          // S fp16: 256 rows x 128B, XOR-swizzled 16B granules (32KB)
#define W0_OFF     32768      // W buf0: fp16 [co][c] 8KB
#define W1_OFF     40960      // W buf1
#define SW_OFF     49152      // packed half2 corner weights 4x256 u32 (4KB)
#define SIDX_OFF   53248      // corner indices 4x256 i32 (4KB)
#define SMEM_BYTES 57344

// ---- scratch (__device__ globals: allocation-free rule) ----
__device__ __half g_xh[(size_t)B_ * HW_ * C_];                   // NHWC fp16
__device__ __align__(16) unsigned char g_w[KK_ * 8192];          // per tap: fp16 [co][c], pre-swizzled

// ---------------- helpers ----------------
__device__ __forceinline__ uint32_t smem_u32(const void* p) {
    uint32_t a;
    asm("{ .reg .u64 t; cvta.to.shared.u64 t, %1; cvt.u32.u64 %0, t; }" : "=r"(a) : "l"(p));
    return a;
}
__device__ __forceinline__ uint32_t pack_f16(float lo, float hi) {
    uint32_t r;
    asm("cvt.rn.f16x2.f32 %0, %1, %2;" : "=r"(r) : "f"(hi), "f"(lo));
    return r;
}
__device__ __forceinline__ __half2 u2h2(uint32_t u) {
    __half2 h;
    *(uint32_t*)&h = u;
    return h;
}
__device__ __forceinline__ uint32_t h22u(__half2 h) { return *(uint32_t*)&h; }
__device__ __forceinline__ void ldsm_x4(uint32_t* r, uint32_t addr) {
    asm volatile("ldmatrix.sync.aligned.m8n8.x4.shared.b16 {%0,%1,%2,%3}, [%4];"
                 : "=r"(r[0]), "=r"(r[1]), "=r"(r[2]), "=r"(r[3]) : "r"(addr));
}
__device__ __forceinline__ void mma_f16(float* d, const uint32_t* a, uint32_t b0, uint32_t b1) {
    asm volatile(
        "mma.sync.aligned.m16n8k16.row.col.f32.f16.f16.f32 "
        "{%0,%1,%2,%3}, {%4,%5,%6,%7}, {%8,%9}, {%0,%1,%2,%3};"
        : "+f"(d[0]), "+f"(d[1]), "+f"(d[2]), "+f"(d[3])
        : "r"(a[0]), "r"(a[1]), "r"(a[2]), "r"(a[3]), "r"(b0), "r"(b1));
}
__device__ __forceinline__ void cp_async16(uint32_t dst, const void* src) {
    asm volatile("cp.async.ca.shared.global [%0], [%1], 16;" :: "r"(dst), "l"(src) : "memory");
}

// ---------------- prepass: NCHW f32 -> NHWC fp16 (proven R8 version) ----------------
__global__ void transpose_x_kernel(const float* __restrict__ x) {
    __shared__ float tile[32][33];
    const int b    = blockIdx.z;
    const int pix0 = blockIdx.x * 32;
    const int c0   = blockIdx.y * 32;
    const int tx = threadIdx.x, ty = threadIdx.y;
#pragma unroll
    for (int i = 0; i < 32; i += 8)
        tile[ty + i][tx] = x[(size_t)(b * C_ + c0 + ty + i) * HW_ + pix0 + tx];
    __syncthreads();
#pragma unroll
    for (int i = 0; i < 32; i += 8)
        g_xh[(size_t)(b * HW_ + pix0 + ty + i) * C_ + c0 + tx] = __float2half_rn(tile[tx][ty + i]);
}

// ---------------- prepass: weight -> fp16, swizzled [k][co][c] ----------------
__global__ void prep_w_kernel(const float* __restrict__ w) {
    int t = blockIdx.x * blockDim.x + threadIdx.x;
    if (t >= KK_ * COUT_ * C_) return;
    int k  = t >> 12;
    int r  = t & 4095;
    int co = r >> 6;
    int c  = r & 63;
    float v = w[co * (C_ * KK_) + c * KK_ + k];
    int jsw  = (c >> 3) ^ (co & 7);
    int off  = co * 128 + jsw * 16 + (c & 7) * 2;
    *(__half*)(g_w + k * 8192 + off) = __float2half_rn(v);
}

// ---------------- fused deformable conv ----------------
// One CTA per (b, ho-pair): M = 256 pixels x 64 cout. 256 threads = 8 warps.
__global__ __launch_bounds__(256, 2) void deform_main_kernel(
    const float* __restrict__ offset,
    const float* __restrict__ mask,
    const float* __restrict__ bias,
    float* __restrict__ out) {
    extern __shared__ char sm[];
    const uint32_t smb = smem_u32(sm);
    uint32_t* swp = (uint32_t*)(sm + SW_OFF);
    int*      sidx = (int*)(sm + SIDX_OFF);

    const int tid = threadIdx.x;
    const int wid = tid >> 5;
    const int l   = tid & 31;
    const int blk = blockIdx.x;          // 0..255
    const int b   = blk >> 6;
    const int ho0 = (blk & 63) * 2;

    const __half* __restrict__ xb = g_xh + (size_t)b * (HW_ * C_);

    const int pm0 = (wid & 3) * 64;      // 4 M-warps x 2 N-warps; tile 64px x 32co
    const int co0 = (wid >> 2) * 32;
    const int lrow = l & 15, lhi = l >> 4, lm = lrow & 7;

    float acc[4][4][4];
#pragma unroll
    for (int i = 0; i < 4; ++i)
#pragma unroll
        for (int j = 0; j < 4; ++j)
#pragma unroll
            for (int q = 0; q < 4; ++q) acc[i][j][q] = 0.f;

    auto coords = [&](int k) {
        const int p   = tid;
        const int row = p >> 7;
        const int ho  = ho0 + row;
        const int wo  = p & 127;
        int obase = ((b * 18 + 2 * k) * 128 + ho) * 128 + wo;
        float dy = offset[obase];
        float dx = offset[obase + HW_];
        float m  = mask[((b * 9 + k) * 128 + ho) * 128 + wo];
        float yy = (float)(ho - 1 + (k / 3)) + dy;
        float xx = (float)(wo - 1 + (k % 3)) + dx;
        float y0f = floorf(yy), x0f = floorf(xx);
        float ly = yy - y0f, lx = xx - x0f;
        int y0 = (int)y0f, x0 = (int)x0f;
        int y1 = y0 + 1,   x1 = x0 + 1;
        bool vy0 = (y0 >= 0) & (y0 < H_), vy1 = (y1 >= 0) & (y1 < H_);
        bool vx0 = (x0 >= 0) & (x0 < W_), vx1 = (x1 >= 0) & (x1 < W_);
        int cy0 = min(max(y0, 0), H_ - 1), cy1 = min(max(y1, 0), H_ - 1);
        int cx0 = min(max(x0, 0), W_ - 1), cx1 = min(max(x1, 0), W_ - 1);
        float w00 = (vy0 & vx0) ? (1.f - ly) * (1.f - lx) * m : 0.f;
        float w01 = (vy0 & vx1) ? (1.f - ly) * lx * m : 0.f;
        float w10 = (vy1 & vx0) ? ly * (1.f - lx) * m : 0.f;
        float w11 = (vy1 & vx1) ? ly * lx * m : 0.f;
        swp[0 * 256 + p] = pack_f16(w00, w00);
        swp[1 * 256 + p] = pack_f16(w01, w01);
        swp[2 * 256 + p] = pack_f16(w10, w10);
        swp[3 * 256 + p] = pack_f16(w11, w11);
        sidx[0 * 256 + p] = (cy0 * W_ + cx0) * C_;
        sidx[1 * 256 + p] = (cy0 * W_ + cx1) * C_;
        sidx[2 * 256 + p] = (cy1 * W_ + cx0) * C_;
        sidx[3 * 256 + p] = (cy1 * W_ + cx1) * C_;
    };
    auto load_w = [&](int k, uint32_t woff) {
        const unsigned char* src = g_w + k * 8192 + tid * 16;
        cp_async16(smb + woff + tid * 16, src);
        cp_async16(smb + woff + tid * 16 + 4096, src + 4096);
        asm volatile("cp.async.commit_group;" ::: "memory");
    };

    // ---- prologue: tap 0 coords + weights ----
    load_w(0, W0_OFF);
    coords(0);
    asm volatile("cp.async.wait_group 0;" ::: "memory");
    __syncthreads();

    for (int k = 0; k < KK_; ++k) {
        const uint32_t wcur = (k & 1) ? W1_OFF : W0_OFF;

        // ---- sample: fp16 gathers + half2 bilinear combine -> swizzled S tile ----
#pragma unroll
        for (int it = 0; it < 8; ++it) {
            int u  = tid + 256 * it;   // 8 c8-groups x 256 pixels
            int c8 = u & 7;
            int p  = u >> 3;
            __half2 w0 = u2h2(swp[p]),       w1 = u2h2(swp[256 + p]);
            __half2 w2 = u2h2(swp[512 + p]), w3 = u2h2(swp[768 + p]);
            int  i0 = sidx[p], i1 = sidx[256 + p], i2 = sidx[512 + p], i3 = sidx[768 + p];
            const __half* xc = xb + c8 * 8;
            uint4 a0 = *(const uint4*)(xc + i0);
            uint4 a1 = *(const uint4*)(xc + i1);
            uint4 a2 = *(const uint4*)(xc + i2);
            uint4 a3 = *(const uint4*)(xc + i3);
            uint32_t res[4];
#pragma unroll
            for (int q = 0; q < 4; ++q) {
                __half2 t = __hmul2(u2h2((&a0.x)[q]), w0);
                t = __hfma2(u2h2((&a1.x)[q]), w1, t);
                t = __hfma2(u2h2((&a2.x)[q]), w2, t);
                t = __hfma2(u2h2((&a3.x)[q]), w3, t);
                res[q] = h22u(t);
            }
            int jsw = c8 ^ (p & 7);
            uint32_t off = (uint32_t)(p * 128 + jsw * 16);
            *(uint4*)(sm + S_OFF + off) = make_uint4(res[0], res[1], res[2], res[3]);
        }
        __syncthreads();

        // ---- overlap: prefetch next tap's weights + coords during GEMM ----
        if (k + 1 < KK_) {
            load_w(k + 1, (k & 1) ? W0_OFF : W1_OFF);
            coords(k + 1);
        }

        // ---- fp16 GEMM via mma.sync ----
        const uint32_t aBase = smb + S_OFF + (uint32_t)(pm0 + lrow) * 128;
        const uint32_t bBase = smb + wcur + (uint32_t)(co0 + lrow) * 128;
#pragma unroll
        for (int ks = 0; ks < 4; ++ks) {
            const uint32_t soff = (uint32_t)((((ks << 1) | lhi) ^ lm) << 4);
            uint32_t bh0[4], bh1[4];
            ldsm_x4(bh0, bBase + soff);
            ldsm_x4(bh1, bBase + 2048 + soff);
#pragma unroll
            for (int mf = 0; mf < 4; ++mf) {
                uint32_t ah[4];
                ldsm_x4(ah, aBase + (uint32_t)(mf * 2048) + soff);
                mma_f16(acc[mf][0], ah, bh0[0], bh0[2]);
                mma_f16(acc[mf][1], ah, bh0[1], bh0[3]);
                mma_f16(acc[mf][2], ah, bh1[0], bh1[2]);
                mma_f16(acc[mf][3], ah, bh1[1], bh1[3]);
            }
        }
        if (k + 1 < KK_)
            asm volatile("cp.async.wait_group 0;" ::: "memory");
        __syncthreads();   // protect S / coords / W buffers for next tap
    }

    // ---- epilogue: fragments -> gmem, add bias ----
    const int rr = (l >> 2);
    const int cbase = (l & 3) * 2;
#pragma unroll
    for (int j = 0; j < 4; ++j) {
        int cc = co0 + j * 8 + cbase;
        float b0v = bias[cc], b1v = bias[cc + 1];
        size_t plane0 = (size_t)(b * COUT_ + cc) * HW_;
        size_t plane1 = plane0 + HW_;
#pragma unroll
        for (int mf = 0; mf < 4; ++mf) {
            int px0 = pm0 + mf * 16 + rr;
            int px1 = px0 + 8;
            size_t o00 = plane0 + (size_t)(ho0 + (px0 >> 7)) * W_ + (px0 & 127);
            size_t o01 = plane1 + (size_t)(ho0 + (px0 >> 7)) * W_ + (px0 & 127);
            size_t o10 = plane0 + (size_t)(ho0 + (px1 >> 7)) * W_ + (px1 & 127);
            size_t o11 = plane1 + (size_t)(ho0 + (px1 >> 7)) * W_ + (px1 & 127);
            out[o00] = acc[mf][j][0] + b0v;
            out[o01] = acc[mf][j][1] + b1v;
            out[o10] = acc[mf][j][2] + b0v;
            out[o11] = acc[mf][j][3] + b1v;
        }
    }
}

extern "C" void kernel_launch(void* const* d_in, const int* in_sizes, int n_in,
                              void* d_out, int out_size) {
    const float* x      = (const float*)d_in[0];
    const float* offset = (const float*)d_in[1];
    const float* mask   = (const float*)d_in[2];
    const float* weight = (const float*)d_in[3];
    const float* bias   = (const float*)d_in[4];
    float* out = (float*)d_out;

    transpose_x_kernel<<<dim3(HW_ / 32, C_ / 32, B_), dim3(32, 8)>>>(x);
    prep_w_kernel<<<(KK_ * C_ * COUT_ + 255) / 256, 256>>>(weight);

    cudaFuncSetAttribute(deform_main_kernel,
                         cudaFuncAttributeMaxDynamicSharedMemorySize, SMEM_BYTES);
    deform_main_kernel<<<B_ * (H_ / 2), 256, SMEM_BYTES>>>(offset, mask, bias, out);
}

// round 12
// speedup vs baseline: 1.1335x; 1.0325x over previous
#include <cuda_runtime.h>
#include <cuda_fp16.h>
#include <cstdint>

#define B_    4
#define C_    64
#define H_    128
#define W_    128
#define HW_   16384
#define COUT_ 64
#define KK_   9

// ---- smem byte layout ----
#define S_OFF      0          // S fp16: 256 rows x 128B, XOR-swizzled 16B granules (32KB)
#define W0_OFF     32768      // W buf0: fp16 [co][c] 8KB
#define W1_OFF     40960      // W buf1
#define SW_OFF     49152      // per-pixel uint4 {w00,w01,w10,w11} packed half2 (4KB)
#define SIDX_OFF   53248      // per-pixel uint4 {i0,i1,i2,i3} (4KB)
#define SMEM_BYTES 57344

// ---- scratch (__device__ globals: allocation-free rule) ----
__device__ __half g_xh[(size_t)B_ * HW_ * C_];                   // NHWC fp16
__device__ __align__(16) unsigned char g_w[KK_ * 8192];          // per tap: fp16 [co][c], pre-swizzled

// ---------------- helpers ----------------
__device__ __forceinline__ uint32_t smem_u32(const void* p) {
    uint32_t a;
    asm("{ .reg .u64 t; cvta.to.shared.u64 t, %1; cvt.u32.u64 %0, t; }" : "=r"(a) : "l"(p));
    return a;
}
__device__ __forceinline__ uint32_t pack_f16(float lo, float hi) {
    uint32_t r;
    asm("cvt.rn.f16x2.f32 %0, %1, %2;" : "=r"(r) : "f"(hi), "f"(lo));
    return r;
}
__device__ __forceinline__ __half2 u2h2(uint32_t u) {
    __half2 h;
    *(uint32_t*)&h = u;
    return h;
}
__device__ __forceinline__ uint32_t h22u(__half2 h) { return *(uint32_t*)&h; }
__device__ __forceinline__ void ldsm_x4(uint32_t* r, uint32_t addr) {
    asm volatile("ldmatrix.sync.aligned.m8n8.x4.shared.b16 {%0,%1,%2,%3}, [%4];"
                 : "=r"(r[0]), "=r"(r[1]), "=r"(r[2]), "=r"(r[3]) : "r"(addr));
}
__device__ __forceinline__ void mma_f16(float* d, const uint32_t* a, uint32_t b0, uint32_t b1) {
    asm volatile(
        "mma.sync.aligned.m16n8k16.row.col.f32.f16.f16.f32 "
        "{%0,%1,%2,%3}, {%4,%5,%6,%7}, {%8,%9}, {%0,%1,%2,%3};"
        : "+f"(d[0]), "+f"(d[1]), "+f"(d[2]), "+f"(d[3])
        : "r"(a[0]), "r"(a[1]), "r"(a[2]), "r"(a[3]), "r"(b0), "r"(b1));
}
__device__ __forceinline__ void cp_async16(uint32_t dst, const void* src) {
    asm volatile("cp.async.ca.shared.global [%0], [%1], 16;" :: "r"(dst), "l"(src) : "memory");
}

// ---------------- prepass v3: NCHW f32 -> NHWC fp16 ----------------
// 64ch x 64px tiles; float4 global reads, SCALAR smem (no alignment traps),
// uint4 global stores (512B contiguous per warp).
__global__ void transpose_x_kernel(const float* __restrict__ x) {
    __shared__ float tile[64][65];
    const int b    = blockIdx.y;
    const int pix0 = blockIdx.x * 64;
    const int tid  = threadIdx.x;

    // read: 4 passes x (16 rows, 16 float4-cols)
    const int col4 = tid & 15;
    const int c_rd = tid >> 4;           // 0..15
#pragma unroll
    for (int i = 0; i < 4; ++i) {
        int c = c_rd + 16 * i;
        float4 v = *(const float4*)&x[(size_t)(b * C_ + c) * HW_ + pix0 + col4 * 4];
        tile[c][col4 * 4 + 0] = v.x;
        tile[c][col4 * 4 + 1] = v.y;
        tile[c][col4 * 4 + 2] = v.z;
        tile[c][col4 * 4 + 3] = v.w;
    }
    __syncthreads();

    // write: 2 passes x (32 px, 8 ch-groups of 8) as uint4
    const int cg = tid & 7;              // channel group (8 ch)
    const int pxl = tid >> 3;            // 0..31
#pragma unroll
    for (int i = 0; i < 2; ++i) {
        int px = pxl + 32 * i;
        int c  = cg * 8;
        uint32_t h0 = pack_f16(tile[c + 0][px], tile[c + 1][px]);
        uint32_t h1 = pack_f16(tile[c + 2][px], tile[c + 3][px]);
        uint32_t h2 = pack_f16(tile[c + 4][px], tile[c + 5][px]);
        uint32_t h3 = pack_f16(tile[c + 6][px], tile[c + 7][px]);
        *(uint4*)&g_xh[(size_t)(b * HW_ + pix0 + px) * C_ + c] = make_uint4(h0, h1, h2, h3);
    }
}

// ---------------- prepass: weight -> fp16, swizzled [k][co][c] ----------------
__global__ void prep_w_kernel(const float* __restrict__ w) {
    int t = blockIdx.x * blockDim.x + threadIdx.x;
    if (t >= KK_ * COUT_ * C_) return;
    int k  = t >> 12;
    int r  = t & 4095;
    int co = r >> 6;
    int c  = r & 63;
    float v = w[co * (C_ * KK_) + c * KK_ + k];
    int jsw  = (c >> 3) ^ (co & 7);
    int off  = co * 128 + jsw * 16 + (c & 7) * 2;
    *(__half*)(g_w + k * 8192 + off) = __float2half_rn(v);
}

// ---------------- fused deformable conv ----------------
// One CTA per (b, ho-pair): M = 256 pixels x 64 cout. 256 threads = 8 warps.
__global__ __launch_bounds__(256, 2) void deform_main_kernel(
    const float* __restrict__ offset,
    const float* __restrict__ mask,
    const float* __restrict__ bias,
    float* __restrict__ out) {
    extern __shared__ char sm[];
    const uint32_t smb = smem_u32(sm);

    const int tid = threadIdx.x;
    const int wid = tid >> 5;
    const int l   = tid & 31;
    const int blk = blockIdx.x;          // 0..255
    const int b   = blk >> 6;
    const int ho0 = (blk & 63) * 2;

    const __half* __restrict__ xb = g_xh + (size_t)b * (HW_ * C_);

    const int pm0 = (wid & 3) * 64;      // 4 M-warps x 2 N-warps; tile 64px x 32co
    const int co0 = (wid >> 2) * 32;
    const int lrow = l & 15, lhi = l >> 4, lm = lrow & 7;

    float acc[4][4][4];
#pragma unroll
    for (int i = 0; i < 4; ++i)
#pragma unroll
        for (int j = 0; j < 4; ++j)
#pragma unroll
            for (int q = 0; q < 4; ++q) acc[i][j][q] = 0.f;

    auto coords = [&](int k) {
        const int p   = tid;
        const int row = p >> 7;
        const int ho  = ho0 + row;
        const int wo  = p & 127;
        int obase = ((b * 18 + 2 * k) * 128 + ho) * 128 + wo;
        float dy = offset[obase];
        float dx = offset[obase + HW_];
        float m  = mask[((b * 9 + k) * 128 + ho) * 128 + wo];
        float yy = (float)(ho - 1 + (k / 3)) + dy;
        float xx = (float)(wo - 1 + (k % 3)) + dx;
        float y0f = floorf(yy), x0f = floorf(xx);
        float ly = yy - y0f, lx = xx - x0f;
        int y0 = (int)y0f, x0 = (int)x0f;
        int y1 = y0 + 1,   x1 = x0 + 1;
        bool vy0 = (y0 >= 0) & (y0 < H_), vy1 = (y1 >= 0) & (y1 < H_);
        bool vx0 = (x0 >= 0) & (x0 < W_), vx1 = (x1 >= 0) & (x1 < W_);
        int cy0 = min(max(y0, 0), H_ - 1), cy1 = min(max(y1, 0), H_ - 1);
        int cx0 = min(max(x0, 0), W_ - 1), cx1 = min(max(x1, 0), W_ - 1);
        float w00 = (vy0 & vx0) ? (1.f - ly) * (1.f - lx) * m : 0.f;
        float w01 = (vy0 & vx1) ? (1.f - ly) * lx * m : 0.f;
        float w10 = (vy1 & vx0) ? ly * (1.f - lx) * m : 0.f;
        float w11 = (vy1 & vx1) ? ly * lx * m : 0.f;
        *(uint4*)(sm + SW_OFF + p * 16) =
            make_uint4(pack_f16(w00, w00), pack_f16(w01, w01),
                       pack_f16(w10, w10), pack_f16(w11, w11));
        *(uint4*)(sm + SIDX_OFF + p * 16) =
            make_uint4((uint32_t)((cy0 * W_ + cx0) * C_), (uint32_t)((cy0 * W_ + cx1) * C_),
                       (uint32_t)((cy1 * W_ + cx0) * C_), (uint32_t)((cy1 * W_ + cx1) * C_));
    };
    auto load_w = [&](int k, uint32_t woff) {
        const unsigned char* src = g_w + k * 8192 + tid * 16;
        cp_async16(smb + woff + tid * 16, src);
        cp_async16(smb + woff + tid * 16 + 4096, src + 4096);
        asm volatile("cp.async.commit_group;" ::: "memory");
    };

    // ---- prologue: tap 0 coords + weights ----
    load_w(0, W0_OFF);
    coords(0);
    asm volatile("cp.async.wait_group 0;" ::: "memory");
    __syncthreads();

    for (int k = 0; k < KK_; ++k) {
        const uint32_t wcur = (k & 1) ? W1_OFF : W0_OFF;

        // ---- sample: fp16 gathers + half2 bilinear combine -> swizzled S tile ----
#pragma unroll
        for (int it = 0; it < 8; ++it) {
            int u  = tid + 256 * it;   // 8 c8-groups x 256 pixels
            int c8 = u & 7;
            int p  = u >> 3;
            uint4 wq = *(const uint4*)(sm + SW_OFF + p * 16);
            uint4 iq = *(const uint4*)(sm + SIDX_OFF + p * 16);
            const __half* xc = xb + c8 * 8;
            uint4 a0 = *(const uint4*)(xc + iq.x);
            uint4 a1 = *(const uint4*)(xc + iq.y);
            uint4 a2 = *(const uint4*)(xc + iq.z);
            uint4 a3 = *(const uint4*)(xc + iq.w);
            __half2 w0 = u2h2(wq.x), w1 = u2h2(wq.y), w2 = u2h2(wq.z), w3 = u2h2(wq.w);
            uint32_t res[4];
#pragma unroll
            for (int q = 0; q < 4; ++q) {
                __half2 t = __hmul2(u2h2((&a0.x)[q]), w0);
                t = __hfma2(u2h2((&a1.x)[q]), w1, t);
                t = __hfma2(u2h2((&a2.x)[q]), w2, t);
                t = __hfma2(u2h2((&a3.x)[q]), w3, t);
                res[q] = h22u(t);
            }
            int jsw = c8 ^ (p & 7);
            uint32_t off = (uint32_t)(p * 128 + jsw * 16);
            *(uint4*)(sm + S_OFF + off) = make_uint4(res[0], res[1], res[2], res[3]);
        }
        __syncthreads();

        // ---- overlap: prefetch next tap's weights + coords during GEMM ----
        if (k + 1 < KK_) {
            load_w(k + 1, (k & 1) ? W0_OFF : W1_OFF);
            coords(k + 1);
        }

        // ---- fp16 GEMM via mma.sync ----
        const uint32_t aBase = smb + S_OFF + (uint32_t)(pm0 + lrow) * 128;
        const uint32_t bBase = smb + wcur + (uint32_t)(co0 + lrow) * 128;
#pragma unroll
        for (int ks = 0; ks < 4; ++ks) {
            const uint32_t soff = (uint32_t)((((ks << 1) | lhi) ^ lm) << 4);
            uint32_t bh0[4], bh1[4];
            ldsm_x4(bh0, bBase + soff);
            ldsm_x4(bh1, bBase + 2048 + soff);
#pragma unroll
            for (int mf = 0; mf < 4; ++mf) {
                uint32_t ah[4];
                ldsm_x4(ah, aBase + (uint32_t)(mf * 2048) + soff);
                mma_f16(acc[mf][0], ah, bh0[0], bh0[2]);
                mma_f16(acc[mf][1], ah, bh0[1], bh0[3]);
                mma_f16(acc[mf][2], ah, bh1[0], bh1[2]);
                mma_f16(acc[mf][3], ah, bh1[1], bh1[3]);
            }
        }
        if (k + 1 < KK_)
            asm volatile("cp.async.wait_group 0;" ::: "memory");
        __syncthreads();   // protect S / coords / W buffers for next tap
    }

    // ---- epilogue: fragments -> gmem, add bias ----
    const int rr = (l >> 2);
    const int cbase = (l & 3) * 2;
#pragma unroll
    for (int j = 0; j < 4; ++j) {
        int cc = co0 + j * 8 + cbase;
        float b0v = bias[cc], b1v = bias[cc + 1];
        size_t plane0 = (size_t)(b * COUT_ + cc) * HW_;
        size_t plane1 = plane0 + HW_;
#pragma unroll
        for (int mf = 0; mf < 4; ++mf) {
            int px0 = pm0 + mf * 16 + rr;
            int px1 = px0 + 8;
            size_t o00 = plane0 + (size_t)(ho0 + (px0 >> 7)) * W_ + (px0 & 127);
            size_t o01 = plane1 + (size_t)(ho0 + (px0 >> 7)) * W_ + (px0 & 127);
            size_t o10 = plane0 + (size_t)(ho0 + (px1 >> 7)) * W_ + (px1 & 127);
            size_t o11 = plane1 + (size_t)(ho0 + (px1 >> 7)) * W_ + (px1 & 127);
            out[o00] = acc[mf][j][0] + b0v;
            out[o01] = acc[mf][j][1] + b1v;
            out[o10] = acc[mf][j][2] + b0v;
            out[o11] = acc[mf][j][3] + b1v;
        }
    }
}

extern "C" void kernel_launch(void* const* d_in, const int* in_sizes, int n_in,
                              void* d_out, int out_size) {
    const float* x      = (const float*)d_in[0];
    const float* offset = (const float*)d_in[1];
    const float* mask   = (const float*)d_in[2];
    const float* weight = (const float*)d_in[3];
    const float* bias   = (const float*)d_in[4];
    float* out = (float*)d_out;

    transpose_x_kernel<<<dim3(HW_ / 64, B_), 256>>>(x);
    prep_w_kernel<<<(KK_ * C_ * COUT_ + 255) / 256, 256>>>(weight);

    cudaFuncSetAttribute(deform_main_kernel,
                         cudaFuncAttributeMaxDynamicSharedMemorySize, SMEM_BYTES);
    deform_main_kernel<<<B_ * (H_ / 2), 256, SMEM_BYTES>>>(offset, mask, bias, out);
}

// round 13
// speedup vs baseline: 1.2348x; 1.0894x over previous
#include <cuda_runtime.h>
#include <cuda_fp16.h>
#include <cstdint>

#define B_    4
#define C_    64
#define H_    128
#define W_    128
#define HW_   16384
#define COUT_ 64
#define KK_   9

// ---- smem byte layout ----
#define S_OFF      0          // S fp16: 256 rows x 128B, XOR-swizzled 16B granules (32KB)
#define W0_OFF     32768      // W buf0: fp16 [co][c] 8KB
#define W1_OFF     40960      // W buf1
#define SW_OFF     49152      // per-pixel uint4 {w00,w01,w10,w11} packed half2 (4KB)
#define SIDX_OFF   53248      // per-pixel uint4 {i0,i1,i2,i3} (4KB)
#define SMEM_BYTES 57344

// ---- scratch (__device__ globals: allocation-free rule) ----
__device__ __half g_xh[(size_t)B_ * HW_ * C_];                   // NHWC fp16
__device__ __align__(16) unsigned char g_w[KK_ * 8192];          // per tap: fp16 [co][c], pre-swizzled

// ---------------- helpers ----------------
__device__ __forceinline__ uint32_t smem_u32(const void* p) {
    uint32_t a;
    asm("{ .reg .u64 t; cvta.to.shared.u64 t, %1; cvt.u32.u64 %0, t; }" : "=r"(a) : "l"(p));
    return a;
}
__device__ __forceinline__ uint32_t pack_f16(float lo, float hi) {
    uint32_t r;
    asm("cvt.rn.f16x2.f32 %0, %1, %2;" : "=r"(r) : "f"(hi), "f"(lo));
    return r;
}
__device__ __forceinline__ __half2 u2h2(uint32_t u) {
    __half2 h;
    *(uint32_t*)&h = u;
    return h;
}
__device__ __forceinline__ uint32_t h22u(__half2 h) { return *(uint32_t*)&h; }
__device__ __forceinline__ void ldsm_x4(uint32_t* r, uint32_t addr) {
    asm volatile("ldmatrix.sync.aligned.m8n8.x4.shared.b16 {%0,%1,%2,%3}, [%4];"
                 : "=r"(r[0]), "=r"(r[1]), "=r"(r[2]), "=r"(r[3]) : "r"(addr));
}
__device__ __forceinline__ void mma_f16(float* d, const uint32_t* a, uint32_t b0, uint32_t b1) {
    asm volatile(
        "mma.sync.aligned.m16n8k16.row.col.f32.f16.f16.f32 "
        "{%0,%1,%2,%3}, {%4,%5,%6,%7}, {%8,%9}, {%0,%1,%2,%3};"
        : "+f"(d[0]), "+f"(d[1]), "+f"(d[2]), "+f"(d[3])
        : "r"(a[0]), "r"(a[1]), "r"(a[2]), "r"(a[3]), "r"(b0), "r"(b1));
}
__device__ __forceinline__ void cp_async16(uint32_t dst, const void* src) {
    asm volatile("cp.async.ca.shared.global [%0], [%1], 16;" :: "r"(dst), "l"(src) : "memory");
}

// ---------------- prepass v3: NCHW f32 -> NHWC fp16 (proven R12) ----------------
__global__ void transpose_x_kernel(const float* __restrict__ x) {
    __shared__ float tile[64][65];
    const int b    = blockIdx.y;
    const int pix0 = blockIdx.x * 64;
    const int tid  = threadIdx.x;
    const int col4 = tid & 15;
    const int c_rd = tid >> 4;
#pragma unroll
    for (int i = 0; i < 4; ++i) {
        int c = c_rd + 16 * i;
        float4 v = *(const float4*)&x[(size_t)(b * C_ + c) * HW_ + pix0 + col4 * 4];
        tile[c][col4 * 4 + 0] = v.x;
        tile[c][col4 * 4 + 1] = v.y;
        tile[c][col4 * 4 + 2] = v.z;
        tile[c][col4 * 4 + 3] = v.w;
    }
    __syncthreads();
    const int cg = tid & 7;
    const int pxl = tid >> 3;
#pragma unroll
    for (int i = 0; i < 2; ++i) {
        int px = pxl + 32 * i;
        int c  = cg * 8;
        uint32_t h0 = pack_f16(tile[c + 0][px], tile[c + 1][px]);
        uint32_t h1 = pack_f16(tile[c + 2][px], tile[c + 3][px]);
        uint32_t h2 = pack_f16(tile[c + 4][px], tile[c + 5][px]);
        uint32_t h3 = pack_f16(tile[c + 6][px], tile[c + 7][px]);
        *(uint4*)&g_xh[(size_t)(b * HW_ + pix0 + px) * C_ + c] = make_uint4(h0, h1, h2, h3);
    }
}

// ---------------- prepass: weight -> fp16, swizzled [k][co][c] ----------------
__global__ void prep_w_kernel(const float* __restrict__ w) {
    int t = blockIdx.x * blockDim.x + threadIdx.x;
    if (t >= KK_ * COUT_ * C_) return;
    int k  = t >> 12;
    int r  = t & 4095;
    int co = r >> 6;
    int c  = r & 63;
    float v = w[co * (C_ * KK_) + c * KK_ + k];
    int jsw  = (c >> 3) ^ (co & 7);
    int off  = co * 128 + jsw * 16 + (c & 7) * 2;
    *(__half*)(g_w + k * 8192 + off) = __float2half_rn(v);
}

// ---------------- fused deformable conv: 16x16 output tiles ----------------
// One CTA per (b, 16x16 tile): M = 256 pixels x 64 cout. 256 threads = 8 warps.
// Gather footprint ~60-74KB/CTA, L1-resident across all 9 taps.
__global__ __launch_bounds__(256, 2) void deform_main_kernel(
    const float* __restrict__ offset,
    const float* __restrict__ mask,
    const float* __restrict__ bias,
    float* __restrict__ out) {
    extern __shared__ char sm[];
    const uint32_t smb = smem_u32(sm);

    const int tid = threadIdx.x;
    const int wid = tid >> 5;
    const int l   = tid & 31;
    const int blk = blockIdx.x;          // 0..255
    const int b   = blk >> 6;
    const int tl  = blk & 63;            // 8x8 tiles
    const int ho0 = (tl >> 3) * 16;
    const int wo0 = (tl & 7) * 16;

    const __half* __restrict__ xb = g_xh + (size_t)b * (HW_ * C_);

    const int pm0 = (wid & 3) * 64;      // 4 M-warps x 2 N-warps; tile 64px x 32co
    const int co0 = (wid >> 2) * 32;
    const int lrow = l & 15, lhi = l >> 4, lm = lrow & 7;

    float acc[4][4][4];
#pragma unroll
    for (int i = 0; i < 4; ++i)
#pragma unroll
        for (int j = 0; j < 4; ++j)
#pragma unroll
            for (int q = 0; q < 4; ++q) acc[i][j][q] = 0.f;

    auto coords = [&](int k) {
        const int p  = tid;
        const int ho = ho0 + (p >> 4);
        const int wo = wo0 + (p & 15);
        int obase = ((b * 18 + 2 * k) * 128 + ho) * 128 + wo;
        float dy = offset[obase];
        float dx = offset[obase + HW_];
        float m  = mask[((b * 9 + k) * 128 + ho) * 128 + wo];
        float yy = (float)(ho - 1 + (k / 3)) + dy;
        float xx = (float)(wo - 1 + (k % 3)) + dx;
        float y0f = floorf(yy), x0f = floorf(xx);
        float ly = yy - y0f, lx = xx - x0f;
        int y0 = (int)y0f, x0 = (int)x0f;
        int y1 = y0 + 1,   x1 = x0 + 1;
        bool vy0 = (y0 >= 0) & (y0 < H_), vy1 = (y1 >= 0) & (y1 < H_);
        bool vx0 = (x0 >= 0) & (x0 < W_), vx1 = (x1 >= 0) & (x1 < W_);
        int cy0 = min(max(y0, 0), H_ - 1), cy1 = min(max(y1, 0), H_ - 1);
        int cx0 = min(max(x0, 0), W_ - 1), cx1 = min(max(x1, 0), W_ - 1);
        float w00 = (vy0 & vx0) ? (1.f - ly) * (1.f - lx) * m : 0.f;
        float w01 = (vy0 & vx1) ? (1.f - ly) * lx * m : 0.f;
        float w10 = (vy1 & vx0) ? ly * (1.f - lx) * m : 0.f;
        float w11 = (vy1 & vx1) ? ly * lx * m : 0.f;
        *(uint4*)(sm + SW_OFF + p * 16) =
            make_uint4(pack_f16(w00, w00), pack_f16(w01, w01),
                       pack_f16(w10, w10), pack_f16(w11, w11));
        *(uint4*)(sm + SIDX_OFF + p * 16) =
            make_uint4((uint32_t)((cy0 * W_ + cx0) * C_), (uint32_t)((cy0 * W_ + cx1) * C_),
                       (uint32_t)((cy1 * W_ + cx0) * C_), (uint32_t)((cy1 * W_ + cx1) * C_));
    };
    auto load_w = [&](int k, uint32_t woff) {
        const unsigned char* src = g_w + k * 8192 + tid * 16;
        cp_async16(smb + woff + tid * 16, src);
        cp_async16(smb + woff + tid * 16 + 4096, src + 4096);
        asm volatile("cp.async.commit_group;" ::: "memory");
    };

    // ---- prologue: tap 0 coords + weights ----
    load_w(0, W0_OFF);
    coords(0);
    asm volatile("cp.async.wait_group 0;" ::: "memory");
    __syncthreads();

    for (int k = 0; k < KK_; ++k) {
        const uint32_t wcur = (k & 1) ? W1_OFF : W0_OFF;

        // ---- sample: fp16 gathers + half2 bilinear combine -> swizzled S tile ----
#pragma unroll
        for (int it = 0; it < 8; ++it) {
            int u  = tid + 256 * it;   // 8 c8-groups x 256 pixels
            int c8 = u & 7;
            int p  = u >> 3;
            uint4 wq = *(const uint4*)(sm + SW_OFF + p * 16);
            uint4 iq = *(const uint4*)(sm + SIDX_OFF + p * 16);
            const __half* xc = xb + c8 * 8;
            uint4 a0 = *(const uint4*)(xc + iq.x);
            uint4 a1 = *(const uint4*)(xc + iq.y);
            uint4 a2 = *(const uint4*)(xc + iq.z);
            uint4 a3 = *(const uint4*)(xc + iq.w);
            __half2 w0 = u2h2(wq.x), w1 = u2h2(wq.y), w2 = u2h2(wq.z), w3 = u2h2(wq.w);
            uint32_t res[4];
#pragma unroll
            for (int q = 0; q < 4; ++q) {
                __half2 t = __hmul2(u2h2((&a0.x)[q]), w0);
                t = __hfma2(u2h2((&a1.x)[q]), w1, t);
                t = __hfma2(u2h2((&a2.x)[q]), w2, t);
                t = __hfma2(u2h2((&a3.x)[q]), w3, t);
                res[q] = h22u(t);
            }
            int jsw = c8 ^ (p & 7);
            uint32_t off = (uint32_t)(p * 128 + jsw * 16);
            *(uint4*)(sm + S_OFF + off) = make_uint4(res[0], res[1], res[2], res[3]);
        }
        __syncthreads();

        // ---- overlap: prefetch next tap's weights + coords during GEMM ----
        if (k + 1 < KK_) {
            load_w(k + 1, (k & 1) ? W0_OFF : W1_OFF);
            coords(k + 1);
        }

        // ---- fp16 GEMM via mma.sync ----
        const uint32_t aBase = smb + S_OFF + (uint32_t)(pm0 + lrow) * 128;
        const uint32_t bBase = smb + wcur + (uint32_t)(co0 + lrow) * 128;
#pragma unroll
        for (int ks = 0; ks < 4; ++ks) {
            const uint32_t soff = (uint32_t)((((ks << 1) | lhi) ^ lm) << 4);
            uint32_t bh0[4], bh1[4];
            ldsm_x4(bh0, bBase + soff);
            ldsm_x4(bh1, bBase + 2048 + soff);
#pragma unroll
            for (int mf = 0; mf < 4; ++mf) {
                uint32_t ah[4];
                ldsm_x4(ah, aBase + (uint32_t)(mf * 2048) + soff);
                mma_f16(acc[mf][0], ah, bh0[0], bh0[2]);
                mma_f16(acc[mf][1], ah, bh0[1], bh0[3]);
                mma_f16(acc[mf][2], ah, bh1[0], bh1[2]);
                mma_f16(acc[mf][3], ah, bh1[1], bh1[3]);
            }
        }
        if (k + 1 < KK_)
            asm volatile("cp.async.wait_group 0;" ::: "memory");
        __syncthreads();   // protect S / coords / W buffers for next tap
    }

    // ---- epilogue: fragments -> gmem, add bias ----
    const int rr = (l >> 2);
    const int cbase = (l & 3) * 2;
#pragma unroll
    for (int j = 0; j < 4; ++j) {
        int cc = co0 + j * 8 + cbase;
        float b0v = bias[cc], b1v = bias[cc + 1];
        size_t plane0 = (size_t)(b * COUT_ + cc) * HW_;
        size_t plane1 = plane0 + HW_;
#pragma unroll
        for (int mf = 0; mf < 4; ++mf) {
            int p0 = pm0 + mf * 16 + rr;
            int p1 = p0 + 8;
            size_t o00 = plane0 + (size_t)(ho0 + (p0 >> 4)) * W_ + wo0 + (p0 & 15);
            size_t o01 = plane1 + (size_t)(ho0 + (p0 >> 4)) * W_ + wo0 + (p0 & 15);
            size_t o10 = plane0 + (size_t)(ho0 + (p1 >> 4)) * W_ + wo0 + (p1 & 15);
            size_t o11 = plane1 + (size_t)(ho0 + (p1 >> 4)) * W_ + wo0 + (p1 & 15);
            out[o00] = acc[mf][j][0] + b0v;
            out[o01] = acc[mf][j][1] + b1v;
            out[o10] = acc[mf][j][2] + b0v;
            out[o11] = acc[mf][j][3] + b1v;
        }
    }
}

extern "C" void kernel_launch(void* const* d_in, const int* in_sizes, int n_in,
                              void* d_out, int out_size) {
    const float* x      = (const float*)d_in[0];
    const float* offset = (const float*)d_in[1];
    const float* mask   = (const float*)d_in[2];
    const float* weight = (const float*)d_in[3];
    const float* bias   = (const float*)d_in[4];
    float* out = (float*)d_out;

    transpose_x_kernel<<<dim3(HW_ / 64, B_), 256>>>(x);
    prep_w_kernel<<<(KK_ * C_ * COUT_ + 255) / 256, 256>>>(weight);

    cudaFuncSetAttribute(deform_main_kernel,
                         cudaFuncAttributeMaxDynamicSharedMemorySize, SMEM_BYTES);
    deform_main_kernel<<<B_ * 64, 256, SMEM_BYTES>>>(offset, mask, bias, out);
}